// round 6
// baseline (speedup 1.0000x reference)
#include <cuda_runtime.h>

// Problem constants
constexpr int BATCH = 128;
constexpr int TSEQ  = 512;
constexpr int KIN   = 906;
constexpr int NG    = 16;       // 4*H gates
constexpr int KQ    = 227;      // K quarter (q3 = 225)
constexpr int CHK   = 8;        // k per chunk
constexpr int NCHQ  = 29;       // chunks per quarter (28*8 + rem)
constexpr int PROWS = 256;      // rows per proj block
constexpr int PITCH = 260;      // k-major tile pitch (260 mod 32 = 4 -> conflict-free)

// Scratch (device globals; no allocation allowed)
// K-quarter partials, layout [t][b][j][ifgo]; i/f/o pre-scaled 0.5 (sigmoid fold)
__device__ __align__(16) float g_xph[4][BATCH * TSEQ * NG];
__device__ float g_hf[BATCH * 4];

// ---------- packed fp32x2 helpers (Blackwell FFMA2) ----------
__device__ __forceinline__ unsigned long long fma2(unsigned long long a,
                                                   unsigned long long b,
                                                   unsigned long long c) {
    unsigned long long d;
    asm("fma.rn.f32x2 %0, %1, %2, %3;" : "=l"(d) : "l"(a), "l"(b), "l"(c));
    return d;
}
__device__ __forceinline__ void unpack2(unsigned long long a, float& lo, float& hi) {
    asm("mov.b64 {%0, %1}, %2;" : "=f"(lo), "=f"(hi) : "l"(a));
}

// ---------- activations ----------
__device__ __forceinline__ float tanha(float x) {
    float r;
    asm("tanh.approx.f32 %0, %1;" : "=f"(r) : "f"(x));
    return r;
}
__device__ __forceinline__ float sigmoid_acc(float x) {
    float e = __expf(-x);
    return __fdividef(1.0f, 1.0f + e);
}
__device__ __forceinline__ float tanh_acc(float x) {
    float e = __expf(2.0f * x);
    return 1.0f - __fdividef(2.0f, 1.0f + e);
}

// =====================================================================
// Kernel 1: projection. grid (256, 4); 128 threads; launch_bounds(128,7).
// Thread owns 8 rows x 4 gates. x tile k-major [k][row] (row-pair FFMA2,
// no packing); W tile duplicated pairs [k][2g] (fp32x2 operands direct).
// Per k: 2 LDS.128 (x) + 2 LDS.128 (W) + 16 FFMA2.
// =====================================================================
__global__ __launch_bounds__(128, 7) void proj_kernel(const float* __restrict__ x,
                                                      const float* __restrict__ Wih,
                                                      const float* __restrict__ bih,
                                                      const float* __restrict__ bhh) {
    __shared__ __align__(16) float sx[2][CHK * PITCH];   // [buf][k][row]
    __shared__ __align__(16) float sw2[2][CHK * 32];     // [buf][k][2g] duplicated

    const int tid  = threadIdx.x;
    const int lane = tid & 31;
    const int wid  = tid >> 5;
    const int kq   = blockIdx.y;
    const int kb   = kq * KQ;
    const int len  = (kq < 3) ? KQ : (KIN - 3 * KQ);   // 227 or 225
    const size_t row0 = (size_t)blockIdx.x * PROWS;

    // compute-role indices
    const int gq = lane & 3;        // gate group (type): gates 4gq..4gq+3
    const int rg = lane >> 2;       // row group 0..7
    const int rbase = 64 * wid + 8 * rg;

    // staging-role indices
    const int kk_l = lane & 7;      // k within chunk
    const int rs   = lane >> 3;     // row sub 0..3
    const int wg   = tid & 15;      // W gate row
    const int wk   = tid >> 4;      // W k within chunk
    const float wsc = ((wg >> 2) == 2) ? 1.0f : 0.5f;   // g-type unscaled

    unsigned long long acc[4][4];   // [rowpair][gate]
#pragma unroll
    for (int rp = 0; rp < 4; ++rp)
#pragma unroll
        for (int m = 0; m < 4; ++m) acc[rp][m] = 0ull;

    float xreg[16];
    float wval;

    auto ldg_chunk = [&](int ch) {
        const int kloc = ch * CHK + kk_l;
        const bool ok = kloc < len;
        const float* xp = x + (row0 + 64 * wid + rs) * KIN + kb + kloc;
#pragma unroll
        for (int i = 0; i < 16; ++i)
            xreg[i] = ok ? __ldg(xp + (size_t)4 * i * KIN) : 0.0f;
        const int kw = ch * CHK + wk;
        wval = (kw < len) ? wsc * __ldg(Wih + (size_t)wg * KIN + kb + kw) : 0.0f;
    };
    auto sts_chunk = [&](int buf) {
        float* s = sx[buf];
#pragma unroll
        for (int i = 0; i < 16; ++i)
            s[kk_l * PITCH + 64 * wid + rs + 4 * i] = xreg[i];
        float2* w2 = reinterpret_cast<float2*>(sw2[buf]);
        w2[wk * 16 + wg] = make_float2(wval, wval);
    };

#define PROJ_K(SX, SW, KK)                                                     \
    {                                                                          \
        const float4 xa = *(const float4*)((SX) + (KK) * PITCH + rbase);       \
        const float4 xb = *(const float4*)((SX) + (KK) * PITCH + rbase + 4);   \
        const float4 wa = *(const float4*)((SW) + (KK) * 32 + 8 * gq);         \
        const float4 wb = *(const float4*)((SW) + (KK) * 32 + 8 * gq + 4);     \
        const ulonglong2 xu0 = *(const ulonglong2*)&xa;                        \
        const ulonglong2 xu1 = *(const ulonglong2*)&xb;                        \
        const ulonglong2 wu0 = *(const ulonglong2*)&wa;                        \
        const ulonglong2 wu1 = *(const ulonglong2*)&wb;                        \
        acc[0][0] = fma2(xu0.x, wu0.x, acc[0][0]);                             \
        acc[0][1] = fma2(xu0.x, wu0.y, acc[0][1]);                             \
        acc[0][2] = fma2(xu0.x, wu1.x, acc[0][2]);                             \
        acc[0][3] = fma2(xu0.x, wu1.y, acc[0][3]);                             \
        acc[1][0] = fma2(xu0.y, wu0.x, acc[1][0]);                             \
        acc[1][1] = fma2(xu0.y, wu0.y, acc[1][1]);                             \
        acc[1][2] = fma2(xu0.y, wu1.x, acc[1][2]);                             \
        acc[1][3] = fma2(xu0.y, wu1.y, acc[1][3]);                             \
        acc[2][0] = fma2(xu1.x, wu0.x, acc[2][0]);                             \
        acc[2][1] = fma2(xu1.x, wu0.y, acc[2][1]);                             \
        acc[2][2] = fma2(xu1.x, wu1.x, acc[2][2]);                             \
        acc[2][3] = fma2(xu1.x, wu1.y, acc[2][3]);                             \
        acc[3][0] = fma2(xu1.y, wu0.x, acc[3][0]);                             \
        acc[3][1] = fma2(xu1.y, wu0.y, acc[3][1]);                             \
        acc[3][2] = fma2(xu1.y, wu1.x, acc[3][2]);                             \
        acc[3][3] = fma2(xu1.y, wu1.y, acc[3][3]);                             \
    }

    ldg_chunk(0);
    sts_chunk(0);
    __syncthreads();

    for (int ch = 0; ch < NCHQ; ++ch) {
        if (ch + 1 < NCHQ) ldg_chunk(ch + 1);
        const float* sxp = sx[ch & 1];
        const float* swp = sw2[ch & 1];
        if (ch < NCHQ - 1) {
#pragma unroll
            for (int kk = 0; kk < CHK; ++kk) PROJ_K(sxp, swp, kk)
        } else {
            const int rem = len - CHK * (NCHQ - 1);   // 3 or 1
            for (int kk = 0; kk < rem; ++kk) PROJ_K(sxp, swp, kk)
        }
        if (ch + 1 < NCHQ) sts_chunk((ch + 1) & 1);
        __syncthreads();
    }
#undef PROJ_K

    // ---- epilogue: unpack, bias on quarter 0 (type-scaled), scatter store ----
    float bs[4] = {0.f, 0.f, 0.f, 0.f};
    if (kq == 0) {
        const float sc = (gq == 2) ? 1.0f : 0.5f;
#pragma unroll
        for (int m = 0; m < 4; ++m)
            bs[m] = sc * (__ldg(&bih[4 * gq + m]) + __ldg(&bhh[4 * gq + m]));
    }
    float* dst = g_xph[kq];
#pragma unroll
    for (int rp = 0; rp < 4; ++rp) {
        float lo[4], hi[4];
#pragma unroll
        for (int m = 0; m < 4; ++m) {
            unpack2(acc[rp][m], lo[m], hi[m]);
            lo[m] += bs[m]; hi[m] += bs[m];
        }
        const size_t R0 = row0 + rbase + 2 * rp;
        const size_t a0 = (((R0) & 511) * 128 + ((R0) >> 9)) * 16 + gq;
        const size_t R1 = R0 + 1;
        const size_t a1 = (((R1) & 511) * 128 + ((R1) >> 9)) * 16 + gq;
#pragma unroll
        for (int m = 0; m < 4; ++m) {
            dst[a0 + 4 * m] = lo[m];
            dst[a1 + 4 * m] = hi[m];
        }
    }
}

// =====================================================================
// Kernel 2: forward LSTM. 8 blocks x 96 threads:
// warp0 = compute (16 batches, dual stream, 4 lanes/batch),
// warps1-2 = load 4 quarter-partials from gmem, combine in regs, STS
// one combined stream (double-buffered 8-step stages).
// =====================================================================
__global__ __launch_bounds__(96) void lstm_fwd_kernel(const float* __restrict__ Whh) {
    __shared__ __align__(16) float scb[2][8][16][16];   // [buf][step][b][16]

    const int tid = threadIdx.x;
    const int blk_b0 = blockIdx.x * 16;

    if (tid >= 32) {
        // ---------------- combine warps (64 lanes) ----------------
        const int l  = tid - 32;
        const int bb = l >> 2;       // batch 0..15
        const int f4 = l & 3;        // float4 slot 0..3
        auto fill = [&](int s) {
            const int t0 = s * 8;
            const int p = s & 1;
#pragma unroll
            for (int u = 0; u < 8; ++u) {     // u = step within stage
                const size_t ga = (((size_t)(t0 + u) * 128) + blk_b0 + bb) * 16 + 4 * f4;
                const float4 a0 = __ldg((const float4*)(g_xph[0] + ga));
                const float4 a1 = __ldg((const float4*)(g_xph[1] + ga));
                const float4 a2 = __ldg((const float4*)(g_xph[2] + ga));
                const float4 a3 = __ldg((const float4*)(g_xph[3] + ga));
                float4 v;
                v.x = (a0.x + a1.x) + (a2.x + a3.x);
                v.y = (a0.y + a1.y) + (a2.y + a3.y);
                v.z = (a0.z + a1.z) + (a2.z + a3.z);
                v.w = (a0.w + a1.w) + (a2.w + a3.w);
                *reinterpret_cast<float4*>(&scb[p][u][bb][4 * f4]) = v;
            }
        };
        fill(0);
        __syncthreads();
        for (int s = 0; s < 64; ++s) {
            if (s + 1 < 64) fill(s + 1);
            __syncthreads();
        }
    } else {
        // ---------------- compute warp ----------------
        const int j  = tid & 3;
        const int pr = tid >> 2;
        const int bA = pr, bB = pr + 8;

        // 0.25 = 0.5(sigmoid fold) * 0.5(h2 fold); g-gate 0.5 (h2 fold only)
        float wi[4], wf[4], wg[4], wo[4];
#pragma unroll
        for (int k = 0; k < 4; ++k) {
            wi[k] = 0.25f * __ldg(&Whh[(0  + j) * 4 + k]);
            wf[k] = 0.25f * __ldg(&Whh[(4  + j) * 4 + k]);
            wg[k] = 0.50f * __ldg(&Whh[(8  + j) * 4 + k]);
            wo[k] = 0.25f * __ldg(&Whh[(12 + j) * 4 + k]);
        }

        float a0 = 0.f, a1 = 0.f, a2 = 0.f, a3 = 0.f, cA = 0.f, hA2 = 0.f;
        float e0 = 0.f, e1 = 0.f, e2 = 0.f, e3 = 0.f, cB = 0.f, hB2 = 0.f;

        __syncthreads();   // matches combine prologue

        for (int s = 0; s < 64; ++s) {
            const int p = s & 1;
            float4 curA = *reinterpret_cast<const float4*>(&scb[p][0][bA][4 * j]);
            float4 curB = *reinterpret_cast<const float4*>(&scb[p][0][bB][4 * j]);
#pragma unroll
            for (int tt = 0; tt < 8; ++tt) {
                float4 nA, nB;
                if (tt < 7) {
                    nA = *reinterpret_cast<const float4*>(&scb[p][tt + 1][bA][4 * j]);
                    nB = *reinterpret_cast<const float4*>(&scb[p][tt + 1][bB][4 * j]);
                }

                float ipA = fmaf(wi[1], a1, fmaf(wi[0], a0, curA.x)) + fmaf(wi[3], a3, wi[2] * a2);
                float fpA = fmaf(wf[1], a1, fmaf(wf[0], a0, curA.y)) + fmaf(wf[3], a3, wf[2] * a2);
                float gpA = fmaf(wg[1], a1, fmaf(wg[0], a0, curA.z)) + fmaf(wg[3], a3, wg[2] * a2);
                float opA = fmaf(wo[1], a1, fmaf(wo[0], a0, curA.w)) + fmaf(wo[3], a3, wo[2] * a2);
                float ipB = fmaf(wi[1], e1, fmaf(wi[0], e0, curB.x)) + fmaf(wi[3], e3, wi[2] * e2);
                float fpB = fmaf(wf[1], e1, fmaf(wf[0], e0, curB.y)) + fmaf(wf[3], e3, wf[2] * e2);
                float gpB = fmaf(wg[1], e1, fmaf(wg[0], e0, curB.z)) + fmaf(wg[3], e3, wg[2] * e2);
                float opB = fmaf(wo[1], e1, fmaf(wo[0], e0, curB.w)) + fmaf(wo[3], e3, wo[2] * e2);

                const float tiA = tanha(ipA), tfA = tanha(fpA), tgA = tanha(gpA), toA = tanha(opA);
                const float tiB = tanha(ipB), tfB = tanha(fpB), tgB = tanha(gpB), toB = tanha(opB);

                cA = 0.5f * (fmaf(tfA, cA, cA) + fmaf(tiA, tgA, tgA));
                cB = 0.5f * (fmaf(tfB, cB, cB) + fmaf(tiB, tgB, tgB));

                const float tcA = tanha(cA);
                const float tcB = tanha(cB);
                hA2 = fmaf(toA, tcA, tcA);   // = 2*h
                hB2 = fmaf(toB, tcB, tcB);

                a0 = __shfl_sync(0xffffffffu, hA2, 0, 4);
                a1 = __shfl_sync(0xffffffffu, hA2, 1, 4);
                a2 = __shfl_sync(0xffffffffu, hA2, 2, 4);
                a3 = __shfl_sync(0xffffffffu, hA2, 3, 4);
                e0 = __shfl_sync(0xffffffffu, hB2, 0, 4);
                e1 = __shfl_sync(0xffffffffu, hB2, 1, 4);
                e2 = __shfl_sync(0xffffffffu, hB2, 2, 4);
                e3 = __shfl_sync(0xffffffffu, hB2, 3, 4);

                curA = nA; curB = nB;
            }
            __syncthreads();
        }

        if (tid < 32) {
            g_hf[(blk_b0 + bA) * 4 + j] = 0.5f * hA2;
            g_hf[(blk_b0 + bB) * 4 + j] = 0.5f * hB2;
        }
    }
}

// =====================================================================
// Kernel 3: tail. 128 blocks x 384 threads; warp w reduces one live gate
// row (i: 0-3, g: 8-11, o: 12-15). f-gate provably unused (c0 = 0).
// =====================================================================
__global__ __launch_bounds__(384) void tail_kernel(const float* __restrict__ x,
                                                   const float* __restrict__ Wihb,
                                                   const float* __restrict__ bihb,
                                                   const float* __restrict__ bhhb,
                                                   const float* __restrict__ Wout,
                                                   const float* __restrict__ bout,
                                                   float* __restrict__ out) {
    const int b = blockIdx.x;
    const int tid = threadIdx.x;
    const int w = tid >> 5;
    const int l = tid & 31;
    const int gr = (w < 4) ? w : (w + 4);    // gate row: 0-3, 8-11, 12-15

    __shared__ float sg[12];

    const float* xr = x + ((size_t)b * TSEQ + (TSEQ - 1)) * KIN;
    const float* wr = Wihb + (size_t)gr * KIN;

    float a = 0.f;
    for (int k = l; k < KIN; k += 32)
        a = fmaf(__ldg(&xr[k]), __ldg(&wr[k]), a);
#pragma unroll
    for (int s = 16; s > 0; s >>= 1)
        a += __shfl_xor_sync(0xffffffffu, a, s);
    if (l == 0) sg[w] = a + __ldg(&bihb[gr]) + __ldg(&bhhb[gr]);
    __syncthreads();

    if (tid == 0) {
        float hb[4], hf[4];
#pragma unroll
        for (int jj = 0; jj < 4; ++jj) {
            float iv = sigmoid_acc(sg[jj]);
            float gv = tanh_acc(sg[4 + jj]);
            float ov = sigmoid_acc(sg[8 + jj]);
            float cc = iv * gv;                 // c0 = 0 => f-gate drops out
            hb[jj] = ov * tanh_acc(cc);
            hf[jj] = g_hf[b * 4 + jj];
        }
#pragma unroll
        for (int o2 = 0; o2 < 2; ++o2) {
            float s = __ldg(&bout[o2]);
#pragma unroll
            for (int jj = 0; jj < 4; ++jj) {
                s = fmaf(__ldg(&Wout[o2 * 8 + jj]),     hf[jj], s);
                s = fmaf(__ldg(&Wout[o2 * 8 + 4 + jj]), hb[jj], s);
            }
            out[b * 2 + o2] = s;
        }
    }
}

// =====================================================================
extern "C" void kernel_launch(void* const* d_in, const int* in_sizes, int n_in,
                              void* d_out, int out_size) {
    const float* x    = (const float*)d_in[0];
    const float* Wihf = (const float*)d_in[1];
    const float* Whhf = (const float*)d_in[2];
    const float* bihf = (const float*)d_in[3];
    const float* bhhf = (const float*)d_in[4];
    const float* Wihb = (const float*)d_in[5];
    // d_in[6] = W_hh_b: provably unused (backward output only needs step 1 from zero state)
    const float* bihb = (const float*)d_in[7];
    const float* bhhb = (const float*)d_in[8];
    const float* Wout = (const float*)d_in[9];
    const float* bout = (const float*)d_in[10];
    float* out = (float*)d_out;

    dim3 pgrid(BATCH * TSEQ / PROWS, 4);   // (256, 4)
    proj_kernel<<<pgrid, 128>>>(x, Wihf, bihf, bhhf);
    lstm_fwd_kernel<<<8, 96>>>(Whhf);
    tail_kernel<<<BATCH, 384>>>(x, Wihb, bihb, bhhb, Wout, bout, out);
}

// round 8
// speedup vs baseline: 1.0260x; 1.0260x over previous
#include <cuda_runtime.h>

// Problem constants
constexpr int BATCH = 128;
constexpr int TSEQ  = 512;
constexpr int KIN   = 906;
constexpr int NG    = 16;       // 4*H gates
constexpr int KHALF = 453;      // K split
constexpr int CK    = 16;       // k per chunk
constexpr int NCH   = 29;       // 28*16 + 5
constexpr int PITCH = 130;      // k-major x tile pitch: kk*130 + b -> all 32 banks distinct

// Scratch (device globals; no allocation allowed)
// K-half partials, layout [t][b][j][ifgo]; i/f/o pre-scaled 0.5 (sigmoid fold)
__device__ __align__(16) float g_xph[2][BATCH * TSEQ * NG];
__device__ float g_hf[BATCH * 4];
__device__ unsigned g_flag[64];   // per 8-t chunk completion counters (target 16)

// ---------- packed fp32x2 helpers (Blackwell FFMA2) ----------
__device__ __forceinline__ unsigned long long pack2(float x) {
    unsigned long long r;
    asm("mov.b64 %0, {%1, %1};" : "=l"(r) : "f"(x));
    return r;
}
__device__ __forceinline__ unsigned long long fma2(unsigned long long a,
                                                   unsigned long long b,
                                                   unsigned long long c) {
    unsigned long long d;
    asm("fma.rn.f32x2 %0, %1, %2, %3;" : "=l"(d) : "l"(a), "l"(b), "l"(c));
    return d;
}
__device__ __forceinline__ void unpack2(unsigned long long a, float& lo, float& hi) {
    asm("mov.b64 {%0, %1}, %2;" : "=f"(lo), "=f"(hi) : "l"(a));
}

// ---------- activations ----------
__device__ __forceinline__ float tanha(float x) {
    float r;
    asm("tanh.approx.f32 %0, %1;" : "=f"(r) : "f"(x));
    return r;
}
__device__ __forceinline__ float sigmoid_acc(float x) {
    float e = __expf(-x);
    return __fdividef(1.0f, 1.0f + e);
}
__device__ __forceinline__ float tanh_acc(float x) {
    float e = __expf(2.0f * x);
    return 1.0f - __fdividef(2.0f, 1.0f + e);
}

// ---------- cp.async 16B ----------
__device__ __forceinline__ void cp16(void* dst, const void* src) {
    unsigned d = (unsigned)__cvta_generic_to_shared(dst);
    asm volatile("cp.async.cg.shared.global [%0], [%1], 16;" :: "r"(d), "l"(src));
}

// =====================================================================
// Kernel 0: reset flags (graph replays reuse device globals).
// =====================================================================
__global__ void reset_kernel() {
    if (threadIdx.x < 64) g_flag[threadIdx.x] = 0u;
}

// =====================================================================
// proj unit: 1 t x 128 b x half-K. 128 threads. Depth-2 LDG pipeline.
// Thread owns row b=tid (all 16 gates as 8 gate-pair FFMA2 accs).
// W staging: 256 vals/chunk = 128 threads x 2 (k = wk and wk+8).
// =====================================================================
__device__ void proj_unit(float* smem, const float* __restrict__ x,
                          const float* __restrict__ Wih,
                          const float* __restrict__ bih,
                          const float* __restrict__ bhh,
                          int t, int half) {
    float* const sxT[2] = { smem, smem + CK * PITCH };
    float* const swb[2] = { smem + 2 * CK * PITCH, smem + 2 * CK * PITCH + 256 };

    const int tid  = threadIdx.x;
    const int lane = tid & 31;
    const int wid  = tid >> 5;
    const int kb   = half * KHALF;

    const int kk_l = lane & 15;     // k within chunk (staging)
    const int b0   = lane >> 4;     // row sub 0/1 (staging)
    const int wg   = tid & 15;      // W gate row
    const int wk   = tid >> 4;      // W k base (0..7); also covers wk+8
    const float wsc = ((wg >> 2) == 2) ? 1.0f : 0.5f;   // g-type unscaled

    unsigned long long acc[8];
#pragma unroll
    for (int m = 0; m < 8; ++m) acc[m] = 0ull;

    float xr[2][16];     // depth-2 register staging (x)
    float wr2[2][2];     // depth-2 register staging (W, 2 k per thread)

    auto ldg_chunk = [&](int ch, int rb) {
        const int kloc = ch * CK + kk_l;
        const bool ok = kloc < KHALF;
        const float* xp = x + ((size_t)(32 * wid + b0) * TSEQ + t) * KIN + kb + kloc;
#pragma unroll
        for (int i = 0; i < 16; ++i)
            xr[rb][i] = ok ? __ldg(xp + (size_t)2 * i * TSEQ * KIN) : 0.0f;
#pragma unroll
        for (int u = 0; u < 2; ++u) {
            const int kw = ch * CK + wk + 8 * u;
            wr2[rb][u] = (kw < KHALF) ? wsc * __ldg(Wih + (size_t)wg * KIN + kb + kw) : 0.0f;
        }
    };
    auto sts_chunk = [&](int rb, int buf) {
        float* s = sxT[buf];
#pragma unroll
        for (int i = 0; i < 16; ++i)
            s[kk_l * PITCH + 32 * wid + b0 + 2 * i] = xr[rb][i];
#pragma unroll
        for (int u = 0; u < 2; ++u)
            swb[buf][(wk + 8 * u) * 16 + wg] = wr2[rb][u];
    };

#define PROJ_K(SX, SW, KK)                                                     \
    {                                                                          \
        const float xv = (SX)[(KK) * PITCH + tid];                             \
        const unsigned long long xx = pack2(xv);                               \
        const ulonglong2* wp = (const ulonglong2*)((SW) + (KK) * 16);          \
        ulonglong2 wa = wp[0], wb2 = wp[1];                                    \
        acc[0] = fma2(xx, wa.x,  acc[0]);                                      \
        acc[1] = fma2(xx, wa.y,  acc[1]);                                      \
        acc[2] = fma2(xx, wb2.x, acc[2]);                                      \
        acc[3] = fma2(xx, wb2.y, acc[3]);                                      \
        ulonglong2 wc = wp[2], wd = wp[3];                                     \
        acc[4] = fma2(xx, wc.x,  acc[4]);                                      \
        acc[5] = fma2(xx, wc.y,  acc[5]);                                      \
        acc[6] = fma2(xx, wd.x,  acc[6]);                                      \
        acc[7] = fma2(xx, wd.y,  acc[7]);                                      \
    }

    ldg_chunk(0, 0);
    ldg_chunk(1, 1);
    __syncthreads();            // protect smem from previous unit's readers
    sts_chunk(0, 0);
    __syncthreads();

    for (int ch = 0; ch < NCH; ++ch) {
        if (ch + 2 < NCH) ldg_chunk(ch + 2, ch & 1);   // rb[ch&1] free (already stored)
        const float* sx = sxT[ch & 1];
        const float* sw = swb[ch & 1];
        if (ch < NCH - 1) {
#pragma unroll
            for (int kk = 0; kk < CK; ++kk) PROJ_K(sx, sw, kk)
        } else {
#pragma unroll
            for (int kk = 0; kk < KHALF - CK * (NCH - 1); ++kk) PROJ_K(sx, sw, kk)
        }
        if (ch + 1 < NCH) sts_chunk((ch + 1) & 1, (ch + 1) & 1);
        __syncthreads();
    }
#undef PROJ_K

    // epilogue: unpack, bias (half 0), store [t][b][j][ifgo]
    float v[16];
#pragma unroll
    for (int m = 0; m < 8; ++m) unpack2(acc[m], v[2 * m], v[2 * m + 1]);
    if (half == 0) {
#pragma unroll
        for (int g = 0; g < 16; ++g) {
            const float sc = (g >= 8 && g < 12) ? 1.0f : 0.5f;
            v[g] += sc * (__ldg(&bih[g]) + __ldg(&bhh[g]));
        }
    }
    float* dst = g_xph[half] + ((size_t)t * 128 + tid) * NG;
#pragma unroll
    for (int j = 0; j < 4; ++j)
        *reinterpret_cast<float4*>(dst + 4 * j) =
            make_float4(v[j], v[4 + j], v[8 + j], v[12 + j]);

    // signal: all stores done -> fence -> count
    __syncthreads();
    if (tid == 0) {
        __threadfence();
        atomicAdd(&g_flag[t >> 3], 1u);
    }
}

// =====================================================================
// lstm role: warp0 compute (16 batches, dual stream), warp1 copy
// (flag-gated cp.async, 8-step stages, both halves), warps 2-3 idle.
// =====================================================================
__device__ void lstm_role(float* smem, const float* __restrict__ Whh, int blk) {
    // smem layout: [p][h][tt][bb][16] floats, p=2,h=2,tt=8,bb=16 -> 32 KB
    auto buf_at = [&](int p, int h, int tt, int bb) -> float* {
        return smem + (((((p * 2) + h) * 8 + tt) * 16) + bb) * 16;
    };
    const int tid = threadIdx.x;
    const int wid = tid >> 5;
    const int blk_b0 = blk * 16;

    if (wid == 1) {
        // ---------------- copy warp ----------------
        const int l  = tid & 31;
        const int bb = l & 15;
        const int f0 = (l >> 4) * 8;
        auto wait_flag = [&](int s) {
            while (*(volatile unsigned*)&g_flag[s] < 16u) __nanosleep(128);
            __threadfence();
        };
        auto fill = [&](int s) {
            const int t0 = s * 8;
            const int p = s & 1;
#pragma unroll
            for (int h = 0; h < 2; ++h) {
                const float* base = g_xph[h];
#pragma unroll
                for (int tt = 0; tt < 8; ++tt) {
                    const float* src = base + (((size_t)(t0 + tt) * 128) + blk_b0 + bb) * 16 + f0;
                    float* d = buf_at(p, h, tt, bb) + f0;
                    cp16(d, src);
                    cp16(d + 4, src + 4);
                }
            }
        };
        wait_flag(0);
        fill(0);
        asm volatile("cp.async.commit_group;");
        asm volatile("cp.async.wait_group 0;" ::: "memory");
        __syncthreads();
        for (int s = 0; s < 64; ++s) {
            if (s + 1 < 64) {
                wait_flag(s + 1);
                fill(s + 1);
                asm volatile("cp.async.commit_group;");
                asm volatile("cp.async.wait_group 0;" ::: "memory");
            }
            __syncthreads();
        }
    } else if (wid == 0) {
        // ---------------- compute warp ----------------
        const int j  = tid & 3;
        const int pr = tid >> 2;
        const int bA = pr, bB = pr + 8;

        // 0.25 = 0.5(sigmoid fold) * 0.5(h2 fold); g-gate 0.5 (h2 fold only)
        float wi[4], wf[4], wg[4], wo[4];
#pragma unroll
        for (int k = 0; k < 4; ++k) {
            wi[k] = 0.25f * __ldg(&Whh[(0  + j) * 4 + k]);
            wf[k] = 0.25f * __ldg(&Whh[(4  + j) * 4 + k]);
            wg[k] = 0.50f * __ldg(&Whh[(8  + j) * 4 + k]);
            wo[k] = 0.25f * __ldg(&Whh[(12 + j) * 4 + k]);
        }

        float a0 = 0.f, a1 = 0.f, a2 = 0.f, a3 = 0.f, cA = 0.f, hA2 = 0.f;
        float e0 = 0.f, e1 = 0.f, e2 = 0.f, e3 = 0.f, cB = 0.f, hB2 = 0.f;

        __syncthreads();   // matches copy prologue

        for (int s = 0; s < 64; ++s) {
            const int p = s & 1;
            float4 cA0 = *reinterpret_cast<const float4*>(buf_at(p, 0, 0, bA) + 4 * j);
            float4 cA1 = *reinterpret_cast<const float4*>(buf_at(p, 1, 0, bA) + 4 * j);
            float4 cB0 = *reinterpret_cast<const float4*>(buf_at(p, 0, 0, bB) + 4 * j);
            float4 cB1 = *reinterpret_cast<const float4*>(buf_at(p, 1, 0, bB) + 4 * j);
#pragma unroll
            for (int tt = 0; tt < 8; ++tt) {
                float4 nA0, nA1, nB0, nB1;
                if (tt < 7) {
                    nA0 = *reinterpret_cast<const float4*>(buf_at(p, 0, tt + 1, bA) + 4 * j);
                    nA1 = *reinterpret_cast<const float4*>(buf_at(p, 1, tt + 1, bA) + 4 * j);
                    nB0 = *reinterpret_cast<const float4*>(buf_at(p, 0, tt + 1, bB) + 4 * j);
                    nB1 = *reinterpret_cast<const float4*>(buf_at(p, 1, tt + 1, bB) + 4 * j);
                }

                // balanced trees; half-1 partial folded into second tree
                float ipA = fmaf(wi[1], a1, fmaf(wi[0], a0, cA0.x)) + fmaf(wi[3], a3, fmaf(wi[2], a2, cA1.x));
                float fpA = fmaf(wf[1], a1, fmaf(wf[0], a0, cA0.y)) + fmaf(wf[3], a3, fmaf(wf[2], a2, cA1.y));
                float gpA = fmaf(wg[1], a1, fmaf(wg[0], a0, cA0.z)) + fmaf(wg[3], a3, fmaf(wg[2], a2, cA1.z));
                float opA = fmaf(wo[1], a1, fmaf(wo[0], a0, cA0.w)) + fmaf(wo[3], a3, fmaf(wo[2], a2, cA1.w));
                float ipB = fmaf(wi[1], e1, fmaf(wi[0], e0, cB0.x)) + fmaf(wi[3], e3, fmaf(wi[2], e2, cB1.x));
                float fpB = fmaf(wf[1], e1, fmaf(wf[0], e0, cB0.y)) + fmaf(wf[3], e3, fmaf(wf[2], e2, cB1.y));
                float gpB = fmaf(wg[1], e1, fmaf(wg[0], e0, cB0.z)) + fmaf(wg[3], e3, fmaf(wg[2], e2, cB1.z));
                float opB = fmaf(wo[1], e1, fmaf(wo[0], e0, cB0.w)) + fmaf(wo[3], e3, fmaf(wo[2], e2, cB1.w));

                const float tiA = tanha(ipA), tfA = tanha(fpA), tgA = tanha(gpA), toA = tanha(opA);
                const float tiB = tanha(ipB), tfB = tanha(fpB), tgB = tanha(gpB), toB = tanha(opB);

                cA = 0.5f * (fmaf(tfA, cA, cA) + fmaf(tiA, tgA, tgA));
                cB = 0.5f * (fmaf(tfB, cB, cB) + fmaf(tiB, tgB, tgB));

                const float tcA = tanha(cA);
                const float tcB = tanha(cB);
                hA2 = fmaf(toA, tcA, tcA);   // = 2*h
                hB2 = fmaf(toB, tcB, tcB);

                a0 = __shfl_sync(0xffffffffu, hA2, 0, 4);
                a1 = __shfl_sync(0xffffffffu, hA2, 1, 4);
                a2 = __shfl_sync(0xffffffffu, hA2, 2, 4);
                a3 = __shfl_sync(0xffffffffu, hA2, 3, 4);
                e0 = __shfl_sync(0xffffffffu, hB2, 0, 4);
                e1 = __shfl_sync(0xffffffffu, hB2, 1, 4);
                e2 = __shfl_sync(0xffffffffu, hB2, 2, 4);
                e3 = __shfl_sync(0xffffffffu, hB2, 3, 4);

                cA0 = nA0; cA1 = nA1; cB0 = nB0; cB1 = nB1;
            }
            __syncthreads();
        }

        g_hf[(blk_b0 + bA) * 4 + j] = 0.5f * hA2;
        g_hf[(blk_b0 + bB) * 4 + j] = 0.5f * hB2;
    } else {
        // idle warps: participate in all 65 block syncs
        for (int i = 0; i < 65; ++i) __syncthreads();
    }
}

// =====================================================================
// Kernel 1: fused proj + lstm. Grid 520: blocks 0-7 lstm, 8-519 proj.
// proj worker w does units (t=w>>1, half=w&1) then (t=256+(w>>1), half=w&1)
// -> t<256 available at ~T/2 for lstm overlap.
// =====================================================================
__global__ __launch_bounds__(128, 4) void fused_kernel(const float* __restrict__ x,
                                                       const float* __restrict__ Wih,
                                                       const float* __restrict__ bih,
                                                       const float* __restrict__ bhh,
                                                       const float* __restrict__ Whh) {
    extern __shared__ float smem[];
    const int bid = blockIdx.x;
    if (bid >= 8) {
        const int w = bid - 8;
        proj_unit(smem, x, Wih, bih, bhh, (w >> 1),       w & 1);
        proj_unit(smem, x, Wih, bih, bhh, 256 + (w >> 1), w & 1);
    } else {
        lstm_role(smem, Whh, bid);
    }
}

// =====================================================================
// Kernel 2: tail. 128 blocks x 384 threads; warp w reduces one live gate
// row (i: 0-3, g: 8-11, o: 12-15). f-gate provably unused (c0 = 0).
// =====================================================================
__global__ __launch_bounds__(384) void tail_kernel(const float* __restrict__ x,
                                                   const float* __restrict__ Wihb,
                                                   const float* __restrict__ bihb,
                                                   const float* __restrict__ bhhb,
                                                   const float* __restrict__ Wout,
                                                   const float* __restrict__ bout,
                                                   float* __restrict__ out) {
    const int b = blockIdx.x;
    const int tid = threadIdx.x;
    const int w = tid >> 5;
    const int l = tid & 31;
    const int gr = (w < 4) ? w : (w + 4);    // gate row: 0-3, 8-11, 12-15

    __shared__ float sg[12];

    const float* xr = x + ((size_t)b * TSEQ + (TSEQ - 1)) * KIN;
    const float* wr = Wihb + (size_t)gr * KIN;

    float a = 0.f;
    for (int k = l; k < KIN; k += 32)
        a = fmaf(__ldg(&xr[k]), __ldg(&wr[k]), a);
#pragma unroll
    for (int s = 16; s > 0; s >>= 1)
        a += __shfl_xor_sync(0xffffffffu, a, s);
    if (l == 0) sg[w] = a + __ldg(&bihb[gr]) + __ldg(&bhhb[gr]);
    __syncthreads();

    if (tid == 0) {
        float hb[4], hf[4];
#pragma unroll
        for (int jj = 0; jj < 4; ++jj) {
            float iv = sigmoid_acc(sg[jj]);
            float gv = tanh_acc(sg[4 + jj]);
            float ov = sigmoid_acc(sg[8 + jj]);
            float cc = iv * gv;                 // c0 = 0 => f-gate drops out
            hb[jj] = ov * tanh_acc(cc);
            hf[jj] = g_hf[b * 4 + jj];
        }
#pragma unroll
        for (int o2 = 0; o2 < 2; ++o2) {
            float s = __ldg(&bout[o2]);
#pragma unroll
            for (int jj = 0; jj < 4; ++jj) {
                s = fmaf(__ldg(&Wout[o2 * 8 + jj]),     hf[jj], s);
                s = fmaf(__ldg(&Wout[o2 * 8 + 4 + jj]), hb[jj], s);
            }
            out[b * 2 + o2] = s;
        }
    }
}

// =====================================================================
extern "C" void kernel_launch(void* const* d_in, const int* in_sizes, int n_in,
                              void* d_out, int out_size) {
    const float* x    = (const float*)d_in[0];
    const float* Wihf = (const float*)d_in[1];
    const float* Whhf = (const float*)d_in[2];
    const float* bihf = (const float*)d_in[3];
    const float* bhhf = (const float*)d_in[4];
    const float* Wihb = (const float*)d_in[5];
    // d_in[6] = W_hh_b: provably unused (backward output only needs step 1 from zero state)
    const float* bihb = (const float*)d_in[7];
    const float* bhhb = (const float*)d_in[8];
    const float* Wout = (const float*)d_in[9];
    const float* bout = (const float*)d_in[10];
    float* out = (float*)d_out;

    constexpr int FUSED_SMEM = 2 * 2 * 8 * 16 * 16 * 4;   // 32768 B (covers proj's 18.7 KB too)

    reset_kernel<<<1, 64>>>();
    fused_kernel<<<8 + 512, 128, FUSED_SMEM>>>(x, Wihf, bihf, bhhf, Whhf);
    tail_kernel<<<BATCH, 384>>>(x, Wihb, bihb, bhhb, Wout, bout, out);
}